// round 14
// baseline (speedup 1.0000x reference)
#include <cuda_runtime.h>
#include <cuda_fp16.h>
#include <cstdint>
#include <math.h>

#define BB 2
#define NN 4096
#define DMODEL 512
#define HH 8
#define DH 64
#define MM (BB*NN)          // 8192 rows
#define TQ 128              // attention q tile
#define TK 32               // attention kv tile

// ---------------- scratch ----------------
__device__ float g_q[BB*HH*NN*DH];   // [bh][n][dh]
__device__ float g_k[BB*HH*NN*DH];
__device__ float g_v[BB*HH*NN*DH];
__device__ float g_y[MM*DMODEL];     // attention output, [b*n][d]

// ===========================================================================
// Portable tensor-core helpers (mma.sync f16, sm_80+ — valid at compute_103)
// ===========================================================================
__device__ __forceinline__ uint32_t pack_h2(float lo, float hi) {
    __half2 h = __floats2half2_rn(lo, hi);
    return *reinterpret_cast<uint32_t*>(&h);
}
__device__ __forceinline__ uint32_t pack_hh(__half h0, __half h1) {
    __half2 h = __halves2half2(h0, h1);
    return *reinterpret_cast<uint32_t*>(&h);
}
// D(16x8,f32) += A(16x16,f16,row) * B(16x8,f16,col)
// lane (g=lane>>2, m=lane&3):
//   a0={A[g][2m],A[g][2m+1]}     a1={A[g+8][2m],A[g+8][2m+1]}
//   a2={A[g][2m+8],A[g][2m+9]}   a3={A[g+8][2m+8],A[g+8][2m+9]}
//   b0={B[2m][g],B[2m+1][g]}     b1={B[2m+8][g],B[2m+9][g]}
//   c0=D[g][2m] c1=D[g][2m+1] c2=D[g+8][2m] c3=D[g+8][2m+1]
__device__ __forceinline__ void mma16(float c[4], const uint32_t a[4],
                                      uint32_t b0, uint32_t b1)
{
    asm volatile(
        "mma.sync.aligned.m16n8k16.row.col.f32.f16.f16.f32 "
        "{%0,%1,%2,%3}, {%4,%5,%6,%7}, {%8,%9}, {%0,%1,%2,%3};"
        : "+f"(c[0]), "+f"(c[1]), "+f"(c[2]), "+f"(c[3])
        : "r"(a[0]), "r"(a[1]), "r"(a[2]), "r"(a[3]), "r"(b0), "r"(b1));
}

// ===========================================================================
// Projection GEMM via 3xFP16-split mma (hi*hi + hi*lo + lo*hi, shared f32
// accumulator; A scaled x4, W scaled x256 so split residuals stay normal;
// epilogue rescales by 1/1024):  dst = A[M,512] @ W[512,512]^T + bias
// CTA: 256 thr (8 warps), tile 128x128; warp tile 64(m) x 32(n); k-chunk 16.
// SMEM: As/Ws[128][20]: words 0-7 = hi f16x2 k-pairs, 8-15 = lo, pad 20.
// Fragment reads: addr ≡ 4g'+m mod 32 -> conflict-free.
// ===========================================================================
#define PKC 16
#define ASCALE 4.0f
#define WSCALE 256.0f
#define OSCALE (1.0f / (ASCALE * WSCALE))

__global__ __launch_bounds__(256, 1) void proj_mma_kernel(
    const float* __restrict__ A, const float* __restrict__ W,
    const float* __restrict__ bias, float* __restrict__ dst, int qkv)
{
    __shared__ uint32_t As[128][20];
    __shared__ uint32_t Ws[128][20];

    const int tid  = threadIdx.x;
    const int lane = tid & 31;
    const int w    = tid >> 5;
    const int g    = lane >> 2;
    const int m    = lane & 3;
    const int wm   = w & 1;
    const int wn   = w >> 1;
    const int m0   = blockIdx.y * 128;
    const int e0   = blockIdx.x * 128;

    const int lr = tid >> 1;         // 0..127
    const int lc = (tid & 1) * 8;    // 0 or 8 (k offset)
    const int lw = lc >> 1;          // word offset 0 or 4

    const float* Ap = A + (size_t)(m0 + lr) * DMODEL + lc;
    const float* Wp = W + (size_t)(e0 + lr) * DMODEL + lc;

    float acc[4][4][4];
#pragma unroll
    for (int mi = 0; mi < 4; mi++)
#pragma unroll
        for (int nj = 0; nj < 4; nj++)
#pragma unroll
            for (int j = 0; j < 4; j++) acc[mi][nj][j] = 0.f;

    float4 pa0 = *(const float4*)(Ap);
    float4 pa1 = *(const float4*)(Ap + 4);
    float4 pw0 = *(const float4*)(Wp);
    float4 pw1 = *(const float4*)(Wp + 4);

    for (int c = 0; c < DMODEL / PKC; c++) {
        __syncthreads();
        {
            const float av[8] = {pa0.x, pa0.y, pa0.z, pa0.w,
                                 pa1.x, pa1.y, pa1.z, pa1.w};
            const float wv[8] = {pw0.x, pw0.y, pw0.z, pw0.w,
                                 pw1.x, pw1.y, pw1.z, pw1.w};
#pragma unroll
            for (int j = 0; j < 4; j++) {
                const float x0 = av[2*j] * ASCALE, x1 = av[2*j+1] * ASCALE;
                const __half h0 = __float2half_rn(x0);
                const __half h1 = __float2half_rn(x1);
                As[lr][lw + j]     = pack_hh(h0, h1);
                As[lr][8 + lw + j] = pack_h2(x0 - __half2float(h0),
                                             x1 - __half2float(h1));
                const float y0 = wv[2*j] * WSCALE, y1 = wv[2*j+1] * WSCALE;
                const __half k0 = __float2half_rn(y0);
                const __half k1 = __float2half_rn(y1);
                Ws[lr][lw + j]     = pack_hh(k0, k1);
                Ws[lr][8 + lw + j] = pack_h2(y0 - __half2float(k0),
                                             y1 - __half2float(k1));
            }
        }
        __syncthreads();

        if (c + 1 < DMODEL / PKC) {
            const int k1 = (c + 1) * PKC;
            pa0 = *(const float4*)(Ap + k1);
            pa1 = *(const float4*)(Ap + k1 + 4);
            pw0 = *(const float4*)(Wp + k1);
            pw1 = *(const float4*)(Wp + k1 + 4);
        }

        // one k16 step per chunk, 3 passes
        uint32_t ah[4][4], al[4][4];
#pragma unroll
        for (int mi = 0; mi < 4; mi++) {
            const int r = 64 * wm + 16 * mi + g;
            ah[mi][0] = As[r    ][m];     ah[mi][1] = As[r + 8][m];
            ah[mi][2] = As[r    ][m + 4]; ah[mi][3] = As[r + 8][m + 4];
            al[mi][0] = As[r    ][8 + m];     al[mi][1] = As[r + 8][8 + m];
            al[mi][2] = As[r    ][8 + m + 4]; al[mi][3] = As[r + 8][8 + m + 4];
        }
        uint32_t bh[4][2], bl[4][2];
#pragma unroll
        for (int nj = 0; nj < 4; nj++) {
            const int n = 32 * wn + 8 * nj + g;
            bh[nj][0] = Ws[n][m];     bh[nj][1] = Ws[n][m + 4];
            bl[nj][0] = Ws[n][8 + m]; bl[nj][1] = Ws[n][8 + m + 4];
        }
#pragma unroll
        for (int mi = 0; mi < 4; mi++)
#pragma unroll
            for (int nj = 0; nj < 4; nj++) {
                mma16(acc[mi][nj], ah[mi], bh[nj][0], bh[nj][1]);
                mma16(acc[mi][nj], ah[mi], bl[nj][0], bl[nj][1]);
                mma16(acc[mi][nj], al[mi], bh[nj][0], bh[nj][1]);
            }
    }

    // ---- epilogue: rescale + bias + (optional) qkv scatter ----------------
#pragma unroll
    for (int mi = 0; mi < 4; mi++) {
        const int r0 = m0 + 64 * wm + 16 * mi + g;
#pragma unroll
        for (int nj = 0; nj < 4; nj++) {
            const int e = e0 + 32 * wn + 8 * nj + 2 * m;
            const float b0 = bias[e], b1 = bias[e + 1];
#pragma unroll
            for (int half = 0; half < 2; half++) {
                const int mr = r0 + 8 * half;
                float2 v = make_float2(acc[mi][nj][2*half]   * OSCALE + b0,
                                       acc[mi][nj][2*half+1] * OSCALE + b1);
                if (qkv) {
                    const int bb = mr >> 12;
                    const int n  = mr & (NN - 1);
                    const int h  = e >> 6;
                    const int d  = e & 63;
                    *(float2*)&dst[((size_t)((bb * HH + h) * NN + n)) * DH + d] = v;
                } else {
                    *(float2*)&dst[(size_t)mr * DMODEL + e] = v;
                }
            }
        }
    }
}

// ===========================================================================
// Attention: all-fp16 mma (f32 accumulate), no-max softmax, register P.
// CTA = 128 thr (4 warps); warp w owns q-rows [32w,32w+32) (m32).
// SMEM: Kp[32][36] (f16x2 d-pairs) | Vp[64][20] (f16x2 kv-pairs, d-major).
// S: 4x k16 steps; O: 2x k16 steps with P direct from S D-fragments.
// ===========================================================================
__global__ __launch_bounds__(128, 2)
void attn_mma_kernel(const float* __restrict__ Q, const float* __restrict__ K,
                     const float* __restrict__ V, float* __restrict__ Y)
{
    __shared__ uint32_t Kp[TK][36];    // Kp[kv][p] = {K[kv][2p],K[kv][2p+1]}
    __shared__ uint32_t Vp[DH][20];    // Vp[d][p]  = {V[2p][d],V[2p+1][d]}

    const int tid  = threadIdx.x;
    const int lane = tid & 31;
    const int w    = tid >> 5;        // 0..3
    const int g    = lane >> 2;
    const int m    = lane & 3;
    const int q0   = blockIdx.x * TQ;
    const int bh   = blockIdx.y;

    const float* Qb = Q + (size_t)bh * NN * DH;
    const float* Kb = K + (size_t)bh * NN * DH;
    const float* Vb = V + (size_t)bh * NN * DH;

    // ---- Q tile -> f16 A-fragments in registers (scaled by 1/8) -----------
    // qa[mi][s] = A-frag for k16 step s (d in [16s,16s+16))
    uint32_t qa[2][4][4];
    {
        const float* Qw = Qb + (size_t)(q0 + 32 * w) * DH;
#pragma unroll
        for (int mi = 0; mi < 2; mi++)
#pragma unroll
            for (int s = 0; s < 4; s++) {
                const int r = 16 * mi + g;
                const int c = 16 * s + 2 * m;
                const float2 q00 = *(const float2*)(Qw + (r    ) * DH + c);
                const float2 q10 = *(const float2*)(Qw + (r + 8) * DH + c);
                const float2 q01 = *(const float2*)(Qw + (r    ) * DH + c + 8);
                const float2 q11 = *(const float2*)(Qw + (r + 8) * DH + c + 8);
                qa[mi][s][0] = pack_h2(q00.x * 0.125f, q00.y * 0.125f);
                qa[mi][s][1] = pack_h2(q10.x * 0.125f, q10.y * 0.125f);
                qa[mi][s][2] = pack_h2(q01.x * 0.125f, q01.y * 0.125f);
                qa[mi][s][3] = pack_h2(q11.x * 0.125f, q11.y * 0.125f);
            }
    }

    float oc[2][8][4];
    float l[4];
#pragma unroll
    for (int mi = 0; mi < 2; mi++)
#pragma unroll
        for (int nj = 0; nj < 8; nj++)
#pragma unroll
            for (int j = 0; j < 4; j++) oc[mi][nj][j] = 0.f;
#pragma unroll
    for (int i = 0; i < 4; i++) l[i] = 0.f;

    // K staging indices: 4 float4 per thread
    int fr[4], fc[4];
#pragma unroll
    for (int i = 0; i < 4; i++) {
        const int flat = (i * 128 + tid) * 4;
        fr[i] = flat >> 6;
        fc[i] = flat & 63;
    }
    // V staging: thread handles kv-pair vp, d-chunk [vdb, vdb+8)
    const int vp  = tid & 15;
    const int vdb = (tid >> 4) * 8;
    const float* Vr0 = Vb + (size_t)(2 * vp    ) * DH + vdb;
    const float* Vr1 = Vb + (size_t)(2 * vp + 1) * DH + vdb;

    float4 kr[4], va0, va1, vb0, vb1;
#define ATTN_LDG(tt) do {                                                  \
        const float* Kt = Kb + (size_t)(tt) * TK * DH;                     \
        const size_t vo = (size_t)(tt) * TK * DH;                          \
        _Pragma("unroll")                                                  \
        for (int i = 0; i < 4; i++)                                        \
            kr[i] = *(const float4*)(Kt + fr[i] * DH + fc[i]);             \
        va0 = *(const float4*)(Vr0 + vo);                                  \
        va1 = *(const float4*)(Vr0 + vo + 4);                              \
        vb0 = *(const float4*)(Vr1 + vo);                                  \
        vb1 = *(const float4*)(Vr1 + vo + 4);                              \
    } while (0)

#define ATTN_STS() do {                                                    \
        _Pragma("unroll")                                                  \
        for (int i = 0; i < 4; i++) {                                      \
            Kp[fr[i]][(fc[i] >> 1)    ] = pack_h2(kr[i].x, kr[i].y);       \
            Kp[fr[i]][(fc[i] >> 1) + 1] = pack_h2(kr[i].z, kr[i].w);       \
        }                                                                  \
        const float av[8] = {va0.x, va0.y, va0.z, va0.w,                   \
                             va1.x, va1.y, va1.z, va1.w};                  \
        const float bv[8] = {vb0.x, vb0.y, vb0.z, vb0.w,                   \
                             vb1.x, vb1.y, vb1.z, vb1.w};                  \
        _Pragma("unroll")                                                  \
        for (int j = 0; j < 8; j++)                                        \
            Vp[vdb + j][vp] = pack_h2(av[j], bv[j]);                       \
    } while (0)

    ATTN_LDG(0);   // prefetch tile 0

    const int T = NN / TK;
    for (int t = 0; t < T; t++) {
        __syncthreads();                       // prev tile fully consumed
        ATTN_STS();
        __syncthreads();

        if (t + 1 < T) ATTN_LDG(t + 1);        // hidden under mma

        // ---- S = Q @ K^T : m32 x n32, k=64 (4 f16 k16-steps) --------------
        float sc[2][4][4];
#pragma unroll
        for (int mi = 0; mi < 2; mi++)
#pragma unroll
            for (int nj = 0; nj < 4; nj++)
#pragma unroll
                for (int j = 0; j < 4; j++) sc[mi][nj][j] = 0.f;

#pragma unroll
        for (int s = 0; s < 4; s++) {
            uint32_t b0[4], b1[4];
#pragma unroll
            for (int nj = 0; nj < 4; nj++) {
                b0[nj] = Kp[8 * nj + g][8 * s + m];      // d-pairs 8s+m
                b1[nj] = Kp[8 * nj + g][8 * s + m + 4];  // d-pairs 8s+m+4
            }
#pragma unroll
            for (int mi = 0; mi < 2; mi++)
#pragma unroll
                for (int nj = 0; nj < 4; nj++)
                    mma16(sc[mi][nj], qa[mi][s], b0[nj], b1[nj]);
        }

        // ---- softmax: exp -> f16 A-fragments in registers -----------------
        uint32_t pa[2][4][2];
#pragma unroll
        for (int mi = 0; mi < 2; mi++) {
            float rs0 = 0.f, rs1 = 0.f;
#pragma unroll
            for (int nj = 0; nj < 4; nj++) {
                const float e0 = __expf(sc[mi][nj][0]);
                const float e1 = __expf(sc[mi][nj][1]);
                const float e2 = __expf(sc[mi][nj][2]);
                const float e3 = __expf(sc[mi][nj][3]);
                rs0 += e0 + e1;
                rs1 += e2 + e3;
                pa[mi][nj][0] = pack_h2(e0, e1);   // rows g
                pa[mi][nj][1] = pack_h2(e2, e3);   // rows g+8
            }
            rs0 += __shfl_xor_sync(0xffffffffu, rs0, 1);
            rs0 += __shfl_xor_sync(0xffffffffu, rs0, 2);
            rs1 += __shfl_xor_sync(0xffffffffu, rs1, 1);
            rs1 += __shfl_xor_sync(0xffffffffu, rs1, 2);
            l[2 * mi]     += rs0;
            l[2 * mi + 1] += rs1;
        }

        // ---- O += P @ V : m32 x n64, k=32 (2 f16 k16-steps) ---------------
        // A-frag for k16 step s': {pa[2s'][0], pa[2s'][1], pa[2s'+1][0], pa[2s'+1][1]}
#pragma unroll
        for (int s = 0; s < 2; s++) {
            uint32_t b0[8], b1[8];
#pragma unroll
            for (int nj = 0; nj < 8; nj++) {
                b0[nj] = Vp[8 * nj + g][8 * s + m];      // kv-pairs 8s+m
                b1[nj] = Vp[8 * nj + g][8 * s + m + 4];  // kv-pairs 8s+m+4
            }
#pragma unroll
            for (int mi = 0; mi < 2; mi++) {
                const uint32_t a[4] = {pa[mi][2*s][0], pa[mi][2*s][1],
                                       pa[mi][2*s+1][0], pa[mi][2*s+1][1]};
#pragma unroll
                for (int nj = 0; nj < 8; nj++)
                    mma16(oc[mi][nj], a, b0[nj], b1[nj]);
            }
        }
    }

    // ---- epilogue: O / l -> Y[b][q][h*64 + d] -----------------------------
    const int bb = bh >> 3;
    const int h  = bh & 7;
    float inv[4];
#pragma unroll
    for (int i = 0; i < 4; i++) inv[i] = 1.f / l[i];

#pragma unroll
    for (int mi = 0; mi < 2; mi++) {
        const int r = 32 * w + 16 * mi + g;
        float* y0 = Y + ((size_t)(bb * NN + q0 + r    )) * DMODEL + h * DH;
        float* y1 = Y + ((size_t)(bb * NN + q0 + r + 8)) * DMODEL + h * DH;
#pragma unroll
        for (int nj = 0; nj < 8; nj++) {
            const int c = 8 * nj + 2 * m;
            float2 p0 = make_float2(oc[mi][nj][0] * inv[2 * mi],
                                    oc[mi][nj][1] * inv[2 * mi]);
            float2 p1 = make_float2(oc[mi][nj][2] * inv[2 * mi + 1],
                                    oc[mi][nj][3] * inv[2 * mi + 1]);
            *(float2*)(y0 + c) = p0;
            *(float2*)(y1 + c) = p1;
        }
    }
}

// ===========================================================================
extern "C" void kernel_launch(void* const* d_in, const int* in_sizes, int n_in,
                              void* d_out, int out_size)
{
    const float* x  = (const float*)d_in[0];
    const float* wq = (const float*)d_in[1];
    const float* bq = (const float*)d_in[2];
    const float* wk = (const float*)d_in[3];
    const float* bk = (const float*)d_in[4];
    const float* wv = (const float*)d_in[5];
    const float* bv = (const float*)d_in[6];
    const float* wo = (const float*)d_in[7];
    const float* bo = (const float*)d_in[8];
    float* out = (float*)d_out;

    float *pq, *pk, *pv, *py;
    cudaGetSymbolAddress((void**)&pq, g_q);
    cudaGetSymbolAddress((void**)&pk, g_k);
    cudaGetSymbolAddress((void**)&pv, g_v);
    cudaGetSymbolAddress((void**)&py, g_y);

    const dim3 pg(DMODEL / 128, MM / 128);    // (4, 64)

    proj_mma_kernel<<<pg, 256>>>(x, wq, bq, pq, 1);
    proj_mma_kernel<<<pg, 256>>>(x, wk, bk, pk, 1);
    proj_mma_kernel<<<pg, 256>>>(x, wv, bv, pv, 1);

    attn_mma_kernel<<<dim3(NN / TQ, BB * HH), 128>>>(pq, pk, pv, py);

    proj_mma_kernel<<<pg, 256>>>(py, wo, bo, out, 0);
}

// round 15
// speedup vs baseline: 1.7156x; 1.7156x over previous
#include <cuda_runtime.h>
#include <cuda_fp16.h>
#include <cstdint>
#include <math.h>

#define BB 2
#define NN 4096
#define DMODEL 512
#define HH 8
#define DH 64
#define MM (BB*NN)          // 8192 rows
#define TQ 128              // attention q tile
#define TK 64               // attention kv tile (2 chunks of 32)

// ---------------- scratch ----------------
__device__ __half h_q [BB*HH*NN*DH];   // [bh][n][dh], pre-scaled by 0.125
__device__ __half h_k [BB*HH*NN*DH];   // [bh][n][dh]
__device__ __half h_vt[BB*HH*DH*NN];   // [bh][dh][n]  (V transposed)
__device__ float  g_y [MM*DMODEL];     // attention output, [b*n][d]

// ===========================================================================
// Portable helpers (mma.sync f16 + cp.async, sm_80+ — valid at compute_103)
// ===========================================================================
__device__ __forceinline__ uint32_t pack_h2(float lo, float hi) {
    __half2 h = __floats2half2_rn(lo, hi);
    return *reinterpret_cast<uint32_t*>(&h);
}
__device__ __forceinline__ uint32_t pack_hh(__half h0, __half h1) {
    __half2 h = __halves2half2(h0, h1);
    return *reinterpret_cast<uint32_t*>(&h);
}
// D(16x8,f32) += A(16x16,f16,row) * B(16x8,f16,col)   (layout per R14, proven)
__device__ __forceinline__ void mma16(float c[4], const uint32_t a[4],
                                      uint32_t b0, uint32_t b1)
{
    asm volatile(
        "mma.sync.aligned.m16n8k16.row.col.f32.f16.f16.f32 "
        "{%0,%1,%2,%3}, {%4,%5,%6,%7}, {%8,%9}, {%0,%1,%2,%3};"
        : "+f"(c[0]), "+f"(c[1]), "+f"(c[2]), "+f"(c[3])
        : "r"(a[0]), "r"(a[1]), "r"(a[2]), "r"(a[3]), "r"(b0), "r"(b1));
}
#define CP16(dst_u32, src_ptr) \
    asm volatile("cp.async.cg.shared.global [%0], [%1], 16;" \
                 :: "r"(dst_u32), "l"(src_ptr))
#define CP_COMMIT() asm volatile("cp.async.commit_group;" ::: "memory")
#define CP_WAIT1()  asm volatile("cp.async.wait_group 1;" ::: "memory")
#define CP_WAIT0()  asm volatile("cp.async.wait_group 0;" ::: "memory")

// ===========================================================================
// Projection GEMM via 3xFP16-split mma (EXACT R14 inner, proven numerics).
// Epilogue modes: 0 = f32 row-major (+bias)            [final O proj]
//                 1 = f16 [bh][n][dh], scaled 0.125    [Q]
//                 2 = f16 [bh][n][dh]                  [K]
//                 3 = f16 [bh][dh][n]  (transposed)    [V]
// ===========================================================================
#define PKC 16
#define ASCALE 4.0f
#define WSCALE 256.0f
#define OSCALE (1.0f / (ASCALE * WSCALE))

__global__ __launch_bounds__(256, 1) void proj_mma_kernel(
    const float* __restrict__ A, const float* __restrict__ W,
    const float* __restrict__ bias, float* __restrict__ dstf,
    __half* __restrict__ dsth, int mode)
{
    __shared__ uint32_t As[128][20];
    __shared__ uint32_t Ws[128][20];

    const int tid  = threadIdx.x;
    const int lane = tid & 31;
    const int w    = tid >> 5;
    const int g    = lane >> 2;
    const int m    = lane & 3;
    const int wm   = w & 1;
    const int wn   = w >> 1;
    const int m0   = blockIdx.y * 128;
    const int e0   = blockIdx.x * 128;

    const int lr = tid >> 1;
    const int lc = (tid & 1) * 8;
    const int lw = lc >> 1;

    const float* Ap = A + (size_t)(m0 + lr) * DMODEL + lc;
    const float* Wp = W + (size_t)(e0 + lr) * DMODEL + lc;

    float acc[4][4][4];
#pragma unroll
    for (int mi = 0; mi < 4; mi++)
#pragma unroll
        for (int nj = 0; nj < 4; nj++)
#pragma unroll
            for (int j = 0; j < 4; j++) acc[mi][nj][j] = 0.f;

    float4 pa0 = *(const float4*)(Ap);
    float4 pa1 = *(const float4*)(Ap + 4);
    float4 pw0 = *(const float4*)(Wp);
    float4 pw1 = *(const float4*)(Wp + 4);

    for (int c = 0; c < DMODEL / PKC; c++) {
        __syncthreads();
        {
            const float av[8] = {pa0.x, pa0.y, pa0.z, pa0.w,
                                 pa1.x, pa1.y, pa1.z, pa1.w};
            const float wv[8] = {pw0.x, pw0.y, pw0.z, pw0.w,
                                 pw1.x, pw1.y, pw1.z, pw1.w};
#pragma unroll
            for (int j = 0; j < 4; j++) {
                const float x0 = av[2*j] * ASCALE, x1 = av[2*j+1] * ASCALE;
                const __half h0 = __float2half_rn(x0);
                const __half h1 = __float2half_rn(x1);
                As[lr][lw + j]     = pack_hh(h0, h1);
                As[lr][8 + lw + j] = pack_h2(x0 - __half2float(h0),
                                             x1 - __half2float(h1));
                const float y0 = wv[2*j] * WSCALE, y1 = wv[2*j+1] * WSCALE;
                const __half k0 = __float2half_rn(y0);
                const __half k1 = __float2half_rn(y1);
                Ws[lr][lw + j]     = pack_hh(k0, k1);
                Ws[lr][8 + lw + j] = pack_h2(y0 - __half2float(k0),
                                             y1 - __half2float(k1));
            }
        }
        __syncthreads();

        if (c + 1 < DMODEL / PKC) {
            const int k1 = (c + 1) * PKC;
            pa0 = *(const float4*)(Ap + k1);
            pa1 = *(const float4*)(Ap + k1 + 4);
            pw0 = *(const float4*)(Wp + k1);
            pw1 = *(const float4*)(Wp + k1 + 4);
        }

        uint32_t ah[4][4], al[4][4];
#pragma unroll
        for (int mi = 0; mi < 4; mi++) {
            const int r = 64 * wm + 16 * mi + g;
            ah[mi][0] = As[r    ][m];     ah[mi][1] = As[r + 8][m];
            ah[mi][2] = As[r    ][m + 4]; ah[mi][3] = As[r + 8][m + 4];
            al[mi][0] = As[r    ][8 + m];     al[mi][1] = As[r + 8][8 + m];
            al[mi][2] = As[r    ][8 + m + 4]; al[mi][3] = As[r + 8][8 + m + 4];
        }
        uint32_t bh[4][2], bl[4][2];
#pragma unroll
        for (int nj = 0; nj < 4; nj++) {
            const int n = 32 * wn + 8 * nj + g;
            bh[nj][0] = Ws[n][m];     bh[nj][1] = Ws[n][m + 4];
            bl[nj][0] = Ws[n][8 + m]; bl[nj][1] = Ws[n][8 + m + 4];
        }
#pragma unroll
        for (int mi = 0; mi < 4; mi++)
#pragma unroll
            for (int nj = 0; nj < 4; nj++) {
                mma16(acc[mi][nj], ah[mi], bh[nj][0], bh[nj][1]);
                mma16(acc[mi][nj], ah[mi], bl[nj][0], bl[nj][1]);
                mma16(acc[mi][nj], al[mi], bh[nj][0], bh[nj][1]);
            }
    }

    // ---- epilogue ---------------------------------------------------------
#pragma unroll
    for (int mi = 0; mi < 4; mi++) {
        const int r0 = m0 + 64 * wm + 16 * mi + g;
#pragma unroll
        for (int nj = 0; nj < 4; nj++) {
            const int e = e0 + 32 * wn + 8 * nj + 2 * m;
            const float b0 = bias[e], b1 = bias[e + 1];
#pragma unroll
            for (int half = 0; half < 2; half++) {
                const int mr = r0 + 8 * half;
                float v0 = acc[mi][nj][2*half]   * OSCALE + b0;
                float v1 = acc[mi][nj][2*half+1] * OSCALE + b1;
                if (mode == 0) {
                    *(float2*)&dstf[(size_t)mr * DMODEL + e] =
                        make_float2(v0, v1);
                } else {
                    const int bb = mr >> 12;
                    const int n  = mr & (NN - 1);
                    const int h  = e >> 6;
                    const int d  = e & 63;
                    if (mode == 3) {           // V transposed [bh][dh][n]
                        __half* base = dsth + ((size_t)(bb*HH + h) * DH) * NN + n;
                        base[(size_t)d       * NN] = __float2half_rn(v0);
                        base[(size_t)(d + 1) * NN] = __float2half_rn(v1);
                    } else {                   // Q/K [bh][n][dh]
                        if (mode == 1) { v0 *= 0.125f; v1 *= 0.125f; }
                        __half2 hv = __floats2half2_rn(v0, v1);
                        *(__half2*)&dsth[((size_t)((bb*HH + h) * NN + n)) * DH + d] = hv;
                    }
                }
            }
        }
    }
}

// ===========================================================================
// Attention: all-fp16 mma, no-max softmax, register P (R14 fragment math),
// cp.async double-buffered staging of PRE-CONVERTED f16 K / transposed V.
// CTA = 128 thr (4 warps); warp w owns q-rows [32w,32w+32).  TK=64, 32 tiles.
// SMEM: Ks[2][64][36]w (K rows f16 = S-B frags)  |  Vp[2][64][36]w (Vt rows
// f16 = O-B frags).  Frag addr ≡ 4g+m (mod 32) -> conflict-free.
// ===========================================================================
__global__ __launch_bounds__(128, 2)
void attn_mma_kernel(const __half* __restrict__ Qh,
                     const __half* __restrict__ Kh,
                     const __half* __restrict__ Vth,
                     float* __restrict__ Y)
{
    __shared__ uint32_t Ks[2][64][36];
    __shared__ uint32_t Vp[2][64][36];

    const int tid  = threadIdx.x;
    const int lane = tid & 31;
    const int w    = tid >> 5;
    const int g    = lane >> 2;
    const int m    = lane & 3;
    const int q0   = blockIdx.x * TQ;
    const int bh   = blockIdx.y;

    const __half* Kb  = Kh  + (size_t)bh * NN * DH;
    const __half* Vtb = Vth + (size_t)bh * DH * NN;

    // ---- Q tile -> f16 A-fragments (already scaled in proj) ---------------
    uint32_t qa[2][4][4];
    {
        const __half* Qw = Qh + (size_t)bh * NN * DH
                              + (size_t)(q0 + 32 * w) * DH;
#pragma unroll
        for (int mi = 0; mi < 2; mi++)
#pragma unroll
            for (int s = 0; s < 4; s++) {
                const int r = 16 * mi + g;
                const int c = 16 * s + 2 * m;
                qa[mi][s][0] = *(const uint32_t*)(Qw + (r    ) * DH + c);
                qa[mi][s][1] = *(const uint32_t*)(Qw + (r + 8) * DH + c);
                qa[mi][s][2] = *(const uint32_t*)(Qw + (r    ) * DH + c + 8);
                qa[mi][s][3] = *(const uint32_t*)(Qw + (r + 8) * DH + c + 8);
            }
    }

    float oc[2][8][4];
    float l[4];
#pragma unroll
    for (int mi = 0; mi < 2; mi++)
#pragma unroll
        for (int nj = 0; nj < 8; nj++)
#pragma unroll
            for (int j = 0; j < 4; j++) oc[mi][nj][j] = 0.f;
#pragma unroll
    for (int i = 0; i < 4; i++) l[i] = 0.f;

    // cp.async chunk map: 512 16B-chunks per operand tile, 4 per thread.
    const uint32_t ks_base = (uint32_t)__cvta_generic_to_shared(&Ks[0][0][0]);
    const uint32_t vp_base = (uint32_t)__cvta_generic_to_shared(&Vp[0][0][0]);

#define ATTN_ISSUE(tt, bi) do {                                             \
        _Pragma("unroll")                                                   \
        for (int j = 0; j < 4; j++) {                                       \
            const int ci  = 4 * tid + j;                                    \
            const int row = ci >> 3;                                        \
            const int off = ci & 7;                                         \
            const uint32_t dw = (uint32_t)((((bi) * 64 + row) * 36 + off * 4) * 4); \
            CP16(ks_base + dw, Kb  + ((size_t)((tt) * 64 + row)) * DH + off * 8);   \
            CP16(vp_base + dw, Vtb + (size_t)row * NN + (tt) * 64 + off * 8);       \
        }                                                                   \
        CP_COMMIT();                                                        \
    } while (0)

    ATTN_ISSUE(0, 0);

    const int T = NN / TK;      // 32
    int buf = 0;
    for (int t = 0; t < T; t++) {
        if (t + 1 < T) { ATTN_ISSUE(t + 1, buf ^ 1); CP_WAIT1(); }
        else           { CP_WAIT0(); }
        __syncthreads();                     // tile t visible CTA-wide

        // ---- two 32-kv chunks: S-mma -> exp -> O-mma ----------------------
#pragma unroll
        for (int c2 = 0; c2 < 2; c2++) {
            float sc[2][4][4];
#pragma unroll
            for (int mi = 0; mi < 2; mi++)
#pragma unroll
                for (int nj = 0; nj < 4; nj++)
#pragma unroll
                    for (int j = 0; j < 4; j++) sc[mi][nj][j] = 0.f;

#pragma unroll
            for (int s = 0; s < 4; s++) {
                uint32_t b0[4], b1[4];
#pragma unroll
                for (int nj = 0; nj < 4; nj++) {
                    const int row = 32 * c2 + 8 * nj + g;
                    b0[nj] = Ks[buf][row][8 * s + m];
                    b1[nj] = Ks[buf][row][8 * s + m + 4];
                }
#pragma unroll
                for (int mi = 0; mi < 2; mi++)
#pragma unroll
                    for (int nj = 0; nj < 4; nj++)
                        mma16(sc[mi][nj], qa[mi][s], b0[nj], b1[nj]);
            }

            uint32_t pa[2][4][2];
#pragma unroll
            for (int mi = 0; mi < 2; mi++) {
                float rs0 = 0.f, rs1 = 0.f;
#pragma unroll
                for (int nj = 0; nj < 4; nj++) {
                    const float e0 = __expf(sc[mi][nj][0]);
                    const float e1 = __expf(sc[mi][nj][1]);
                    const float e2 = __expf(sc[mi][nj][2]);
                    const float e3 = __expf(sc[mi][nj][3]);
                    rs0 += e0 + e1;
                    rs1 += e2 + e3;
                    pa[mi][nj][0] = pack_h2(e0, e1);
                    pa[mi][nj][1] = pack_h2(e2, e3);
                }
                rs0 += __shfl_xor_sync(0xffffffffu, rs0, 1);
                rs0 += __shfl_xor_sync(0xffffffffu, rs0, 2);
                rs1 += __shfl_xor_sync(0xffffffffu, rs1, 1);
                rs1 += __shfl_xor_sync(0xffffffffu, rs1, 2);
                l[2 * mi]     += rs0;
                l[2 * mi + 1] += rs1;
            }

            // O += P_chunk @ V_chunk : k=32 (2 f16 k16-steps)
#pragma unroll
            for (int sp = 0; sp < 2; sp++) {
                const int s = 2 * c2 + sp;          // global kv-pair group
                uint32_t b0[8], b1[8];
#pragma unroll
                for (int nj = 0; nj < 8; nj++) {
                    b0[nj] = Vp[buf][8 * nj + g][8 * s + m];
                    b1[nj] = Vp[buf][8 * nj + g][8 * s + m + 4];
                }
#pragma unroll
                for (int mi = 0; mi < 2; mi++) {
                    const uint32_t a[4] = {pa[mi][2*sp][0],   pa[mi][2*sp][1],
                                           pa[mi][2*sp+1][0], pa[mi][2*sp+1][1]};
#pragma unroll
                    for (int nj = 0; nj < 8; nj++)
                        mma16(oc[mi][nj], a, b0[nj], b1[nj]);
                }
            }
        }

        __syncthreads();                     // compute done before buf reuse
        buf ^= 1;
    }

    // ---- epilogue: O / l -> Y[b][q][h*64 + d] -----------------------------
    const int bb = bh >> 3;
    const int h  = bh & 7;
    float inv[4];
#pragma unroll
    for (int i = 0; i < 4; i++) inv[i] = 1.f / l[i];

#pragma unroll
    for (int mi = 0; mi < 2; mi++) {
        const int r = 32 * w + 16 * mi + g;
        float* y0 = Y + ((size_t)(bb * NN + q0 + r    )) * DMODEL + h * DH;
        float* y1 = Y + ((size_t)(bb * NN + q0 + r + 8)) * DMODEL + h * DH;
#pragma unroll
        for (int nj = 0; nj < 8; nj++) {
            const int c = 8 * nj + 2 * m;
            float2 p0 = make_float2(oc[mi][nj][0] * inv[2 * mi],
                                    oc[mi][nj][1] * inv[2 * mi]);
            float2 p1 = make_float2(oc[mi][nj][2] * inv[2 * mi + 1],
                                    oc[mi][nj][3] * inv[2 * mi + 1]);
            *(float2*)(y0 + c) = p0;
            *(float2*)(y1 + c) = p1;
        }
    }
}

// ===========================================================================
extern "C" void kernel_launch(void* const* d_in, const int* in_sizes, int n_in,
                              void* d_out, int out_size)
{
    const float* x  = (const float*)d_in[0];
    const float* wq = (const float*)d_in[1];
    const float* bq = (const float*)d_in[2];
    const float* wk = (const float*)d_in[3];
    const float* bk = (const float*)d_in[4];
    const float* wv = (const float*)d_in[5];
    const float* bv = (const float*)d_in[6];
    const float* wo = (const float*)d_in[7];
    const float* bo = (const float*)d_in[8];
    float* out = (float*)d_out;

    __half *pq, *pk, *pvt;
    float  *py;
    cudaGetSymbolAddress((void**)&pq,  h_q);
    cudaGetSymbolAddress((void**)&pk,  h_k);
    cudaGetSymbolAddress((void**)&pvt, h_vt);
    cudaGetSymbolAddress((void**)&py,  g_y);

    const dim3 pg(DMODEL / 128, MM / 128);    // (4, 64)

    proj_mma_kernel<<<pg, 256>>>(x, wq, bq, nullptr, pq,  1);  // Q f16 *0.125
    proj_mma_kernel<<<pg, 256>>>(x, wk, bk, nullptr, pk,  2);  // K f16
    proj_mma_kernel<<<pg, 256>>>(x, wv, bv, nullptr, pvt, 3);  // V f16, transposed

    attn_mma_kernel<<<dim3(NN / TQ, BB * HH), 128>>>(pq, pk, pvt, py);

    proj_mma_kernel<<<pg, 256>>>(py, wo, bo, out, nullptr, 0); // O f32
}

// round 16
// speedup vs baseline: 1.7827x; 1.0391x over previous
#include <cuda_runtime.h>
#include <cuda_fp16.h>
#include <cstdint>
#include <math.h>

#define BB 2
#define NN 4096
#define DMODEL 512
#define HH 8
#define DH 64
#define MM (BB*NN)          // 8192 rows
#define TQ 128              // attention q tile
#define TK 64               // attention kv tile (2 chunks of 32)

// ---------------- scratch ----------------
__device__ __half s_xh[MM*DMODEL];     // f16(4*x)
__device__ __half s_xl[MM*DMODEL];     // residual
__device__ __half s_wh[4][DMODEL*DMODEL];   // f16(256*W), slots q,k,v,o
__device__ __half s_wl[4][DMODEL*DMODEL];
__device__ __half s_yh[MM*DMODEL];     // f16(4*y) attention output
__device__ __half s_yl[MM*DMODEL];
__device__ __half h_q [BB*HH*NN*DH];   // [bh][n][dh], pre-scaled by 0.125
__device__ __half h_k [BB*HH*NN*DH];   // [bh][n][dh]
__device__ __half h_vt[BB*HH*DH*NN];   // [bh][dh][n]  (V transposed)

// ===========================================================================
// Portable helpers (mma.sync f16 + cp.async, sm_80+ — valid at compute_103)
// ===========================================================================
__device__ __forceinline__ uint32_t pack_h2(float lo, float hi) {
    __half2 h = __floats2half2_rn(lo, hi);
    return *reinterpret_cast<uint32_t*>(&h);
}
// D(16x8,f32) += A(16x16,f16,row) * B(16x8,f16,col)   (layout per R14, proven)
__device__ __forceinline__ void mma16(float c[4], const uint32_t a[4],
                                      uint32_t b0, uint32_t b1)
{
    asm volatile(
        "mma.sync.aligned.m16n8k16.row.col.f32.f16.f16.f32 "
        "{%0,%1,%2,%3}, {%4,%5,%6,%7}, {%8,%9}, {%0,%1,%2,%3};"
        : "+f"(c[0]), "+f"(c[1]), "+f"(c[2]), "+f"(c[3])
        : "r"(a[0]), "r"(a[1]), "r"(a[2]), "r"(a[3]), "r"(b0), "r"(b1));
}
#define CP16(dst_u32, src_ptr) \
    asm volatile("cp.async.cg.shared.global [%0], [%1], 16;" \
                 :: "r"(dst_u32), "l"(src_ptr))
#define CP_COMMIT() asm volatile("cp.async.commit_group;" ::: "memory")
#define CP_WAIT1()  asm volatile("cp.async.wait_group 1;" ::: "memory")
#define CP_WAIT0()  asm volatile("cp.async.wait_group 0;" ::: "memory")

#define ASCALE 4.0f
#define WSCALE 256.0f
#define OSCALE (1.0f / (ASCALE * WSCALE))

// ===========================================================================
// One-time conversion: dst_hi = f16(scale*src), dst_lo = residual.
// ===========================================================================
__global__ __launch_bounds__(256) void conv_split_kernel(
    const float* __restrict__ src, __half* __restrict__ hi,
    __half* __restrict__ lo, float scale, int n2)
{
    const int i = blockIdx.x * 256 + threadIdx.x;
    if (i >= n2) return;
    const float2 v = ((const float2*)src)[i];
    const float a = v.x * scale, b = v.y * scale;
    const __half ha = __float2half_rn(a), hb = __float2half_rn(b);
    ((__half2*)hi)[i] = __halves2half2(ha, hb);
    ((__half2*)lo)[i] = __floats2half2_rn(a - __half2float(ha),
                                          b - __half2float(hb));
}

// ===========================================================================
// Projection GEMM, 3xFP16-split, PRE-CONVERTED inputs + cp.async pipeline:
//   dst = A @ W^T + bias   (A = hi+lo over ASCALE, W = hi+lo over WSCALE)
// CTA: 256 thr (8 warps), tile 128x128; warp tile 64(m) x 32(n); k-chunk 16.
// SMEM (dynamic): As[2][128][20]w | Ws[2][128][20]w  (words 0-7 hi, 8-15 lo)
// Loop per chunk: cp.async(c+1, buf^1) -> wait(1) -> bar -> 48 mma16 -> bar.
// Epilogue modes: 0 = f32 (+bias) [O]; 1 = Q f16*0.125; 2 = K f16; 3 = Vt f16.
// ===========================================================================
#define PKC 16
#define PROJ_SMEM_BYTES (2 * 2 * 128 * 20 * 4)   // 81920

__global__ __launch_bounds__(256, 1) void proj_mma_kernel(
    const __half* __restrict__ Ah, const __half* __restrict__ Al,
    const __half* __restrict__ Wh, const __half* __restrict__ Wl,
    const float* __restrict__ bias, float* __restrict__ dstf,
    __half* __restrict__ dsth, int mode)
{
    extern __shared__ uint32_t psm[];
    uint32_t (*As)[128][20] = (uint32_t(*)[128][20])psm;
    uint32_t (*Ws)[128][20] = (uint32_t(*)[128][20])(psm + 2 * 128 * 20);

    const int tid  = threadIdx.x;
    const int lane = tid & 31;
    const int w    = tid >> 5;
    const int g    = lane >> 2;
    const int m    = lane & 3;
    const int wm   = w & 1;
    const int wn   = w >> 1;
    const int m0   = blockIdx.y * 128;
    const int e0   = blockIdx.x * 128;

    const uint32_t as_base = (uint32_t)__cvta_generic_to_shared(&As[0][0][0]);
    const uint32_t ws_base = (uint32_t)__cvta_generic_to_shared(&Ws[0][0][0]);

    float acc[4][4][4];
#pragma unroll
    for (int mi = 0; mi < 4; mi++)
#pragma unroll
        for (int nj = 0; nj < 4; nj++)
#pragma unroll
            for (int j = 0; j < 4; j++) acc[mi][nj][j] = 0.f;

    // chunk map: 1024 16B-chunks per k-chunk (A:512 + W:512), 4 per thread.
    // ci9 = ci & 511: row = ci9>>2, sub = ci9&3 (0-1 hi halves, 2-3 lo).
#define PROJ_ISSUE(cc, bi) do {                                              \
        _Pragma("unroll")                                                    \
        for (int j = 0; j < 4; j++) {                                        \
            const int ci  = 4 * tid + j;                                     \
            const int op  = ci >> 9;                                         \
            const int ci9 = ci & 511;                                        \
            const int row = ci9 >> 2;                                        \
            const int sub = ci9 & 3;                                         \
            const int woff = (sub < 2) ? sub * 4 : 8 + (sub - 2) * 4;        \
            const uint32_t dw = (uint32_t)(((((bi) * 128 + row) * 20) + woff) * 4); \
            const int ko = (cc) * PKC + (sub & 1) * 8;                       \
            if (op == 0) {                                                   \
                const __half* src = ((sub < 2) ? Ah : Al)                    \
                    + (size_t)(m0 + row) * DMODEL + ko;                      \
                CP16(as_base + dw, src);                                     \
            } else {                                                         \
                const __half* src = ((sub < 2) ? Wh : Wl)                    \
                    + (size_t)(e0 + row) * DMODEL + ko;                      \
                CP16(ws_base + dw, src);                                     \
            }                                                                \
        }                                                                    \
        CP_COMMIT();                                                         \
    } while (0)

    PROJ_ISSUE(0, 0);

    const int NC = DMODEL / PKC;     // 32
    int buf = 0;
    for (int c = 0; c < NC; c++) {
        if (c + 1 < NC) { PROJ_ISSUE(c + 1, buf ^ 1); CP_WAIT1(); }
        else            { CP_WAIT0(); }
        __syncthreads();                    // chunk c visible CTA-wide

        uint32_t ah[4][4], al[4][4];
#pragma unroll
        for (int mi = 0; mi < 4; mi++) {
            const int r = 64 * wm + 16 * mi + g;
            ah[mi][0] = As[buf][r    ][m];     ah[mi][1] = As[buf][r + 8][m];
            ah[mi][2] = As[buf][r    ][m + 4]; ah[mi][3] = As[buf][r + 8][m + 4];
            al[mi][0] = As[buf][r    ][8 + m];     al[mi][1] = As[buf][r + 8][8 + m];
            al[mi][2] = As[buf][r    ][8 + m + 4]; al[mi][3] = As[buf][r + 8][8 + m + 4];
        }
        uint32_t bh[4][2], bl[4][2];
#pragma unroll
        for (int nj = 0; nj < 4; nj++) {
            const int n = 32 * wn + 8 * nj + g;
            bh[nj][0] = Ws[buf][n][m];     bh[nj][1] = Ws[buf][n][m + 4];
            bl[nj][0] = Ws[buf][n][8 + m]; bl[nj][1] = Ws[buf][n][8 + m + 4];
        }
#pragma unroll
        for (int mi = 0; mi < 4; mi++)
#pragma unroll
            for (int nj = 0; nj < 4; nj++) {
                mma16(acc[mi][nj], ah[mi], bh[nj][0], bh[nj][1]);
                mma16(acc[mi][nj], ah[mi], bl[nj][0], bl[nj][1]);
                mma16(acc[mi][nj], al[mi], bh[nj][0], bh[nj][1]);
            }

        __syncthreads();                    // buf consumed before next issue
        buf ^= 1;
    }

    // ---- epilogue ---------------------------------------------------------
#pragma unroll
    for (int mi = 0; mi < 4; mi++) {
        const int r0 = m0 + 64 * wm + 16 * mi + g;
#pragma unroll
        for (int nj = 0; nj < 4; nj++) {
            const int e = e0 + 32 * wn + 8 * nj + 2 * m;
            const float b0 = bias[e], b1 = bias[e + 1];
#pragma unroll
            for (int half = 0; half < 2; half++) {
                const int mr = r0 + 8 * half;
                float v0 = acc[mi][nj][2*half]   * OSCALE + b0;
                float v1 = acc[mi][nj][2*half+1] * OSCALE + b1;
                if (mode == 0) {
                    *(float2*)&dstf[(size_t)mr * DMODEL + e] =
                        make_float2(v0, v1);
                } else {
                    const int bb = mr >> 12;
                    const int n  = mr & (NN - 1);
                    const int h  = e >> 6;
                    const int d  = e & 63;
                    if (mode == 3) {           // V transposed [bh][dh][n]
                        __half* base = dsth + ((size_t)(bb*HH + h) * DH) * NN + n;
                        base[(size_t)d       * NN] = __float2half_rn(v0);
                        base[(size_t)(d + 1) * NN] = __float2half_rn(v1);
                    } else {                   // Q/K [bh][n][dh]
                        if (mode == 1) { v0 *= 0.125f; v1 *= 0.125f; }
                        __half2 hv = __floats2half2_rn(v0, v1);
                        *(__half2*)&dsth[((size_t)((bb*HH + h) * NN + n)) * DH + d] = hv;
                    }
                }
            }
        }
    }
}

// ===========================================================================
// Attention (EXACT R15 structure, proven 269us) — epilogue now emits
// yh = f16(4*y), yl = residual directly (feeds the O-projection pre-split).
// ===========================================================================
__global__ __launch_bounds__(128, 2)
void attn_mma_kernel(const __half* __restrict__ Qh,
                     const __half* __restrict__ Kh,
                     const __half* __restrict__ Vth,
                     __half* __restrict__ Yh, __half* __restrict__ Yl)
{
    __shared__ uint32_t Ks[2][64][36];
    __shared__ uint32_t Vp[2][64][36];

    const int tid  = threadIdx.x;
    const int lane = tid & 31;
    const int w    = tid >> 5;
    const int g    = lane >> 2;
    const int m    = lane & 3;
    const int q0   = blockIdx.x * TQ;
    const int bh   = blockIdx.y;

    const __half* Kb  = Kh  + (size_t)bh * NN * DH;
    const __half* Vtb = Vth + (size_t)bh * DH * NN;

    uint32_t qa[2][4][4];
    {
        const __half* Qw = Qh + (size_t)bh * NN * DH
                              + (size_t)(q0 + 32 * w) * DH;
#pragma unroll
        for (int mi = 0; mi < 2; mi++)
#pragma unroll
            for (int s = 0; s < 4; s++) {
                const int r = 16 * mi + g;
                const int c = 16 * s + 2 * m;
                qa[mi][s][0] = *(const uint32_t*)(Qw + (r    ) * DH + c);
                qa[mi][s][1] = *(const uint32_t*)(Qw + (r + 8) * DH + c);
                qa[mi][s][2] = *(const uint32_t*)(Qw + (r    ) * DH + c + 8);
                qa[mi][s][3] = *(const uint32_t*)(Qw + (r + 8) * DH + c + 8);
            }
    }

    float oc[2][8][4];
    float l[4];
#pragma unroll
    for (int mi = 0; mi < 2; mi++)
#pragma unroll
        for (int nj = 0; nj < 8; nj++)
#pragma unroll
            for (int j = 0; j < 4; j++) oc[mi][nj][j] = 0.f;
#pragma unroll
    for (int i = 0; i < 4; i++) l[i] = 0.f;

    const uint32_t ks_base = (uint32_t)__cvta_generic_to_shared(&Ks[0][0][0]);
    const uint32_t vp_base = (uint32_t)__cvta_generic_to_shared(&Vp[0][0][0]);

#define ATTN_ISSUE(tt, bi) do {                                             \
        _Pragma("unroll")                                                   \
        for (int j = 0; j < 4; j++) {                                       \
            const int ci  = 4 * tid + j;                                    \
            const int row = ci >> 3;                                        \
            const int off = ci & 7;                                         \
            const uint32_t dw = (uint32_t)((((bi) * 64 + row) * 36 + off * 4) * 4); \
            CP16(ks_base + dw, Kb  + ((size_t)((tt) * 64 + row)) * DH + off * 8);   \
            CP16(vp_base + dw, Vtb + (size_t)row * NN + (tt) * 64 + off * 8);       \
        }                                                                   \
        CP_COMMIT();                                                        \
    } while (0)

    ATTN_ISSUE(0, 0);

    const int T = NN / TK;      // 32
    int buf = 0;
    for (int t = 0; t < T; t++) {
        if (t + 1 < T) { ATTN_ISSUE(t + 1, buf ^ 1); CP_WAIT1(); }
        else           { CP_WAIT0(); }
        __syncthreads();

#pragma unroll
        for (int c2 = 0; c2 < 2; c2++) {
            float sc[2][4][4];
#pragma unroll
            for (int mi = 0; mi < 2; mi++)
#pragma unroll
                for (int nj = 0; nj < 4; nj++)
#pragma unroll
                    for (int j = 0; j < 4; j++) sc[mi][nj][j] = 0.f;

#pragma unroll
            for (int s = 0; s < 4; s++) {
                uint32_t b0[4], b1[4];
#pragma unroll
                for (int nj = 0; nj < 4; nj++) {
                    const int row = 32 * c2 + 8 * nj + g;
                    b0[nj] = Ks[buf][row][8 * s + m];
                    b1[nj] = Ks[buf][row][8 * s + m + 4];
                }
#pragma unroll
                for (int mi = 0; mi < 2; mi++)
#pragma unroll
                    for (int nj = 0; nj < 4; nj++)
                        mma16(sc[mi][nj], qa[mi][s], b0[nj], b1[nj]);
            }

            uint32_t pa[2][4][2];
#pragma unroll
            for (int mi = 0; mi < 2; mi++) {
                float rs0 = 0.f, rs1 = 0.f;
#pragma unroll
                for (int nj = 0; nj < 4; nj++) {
                    const float e0 = __expf(sc[mi][nj][0]);
                    const float e1 = __expf(sc[mi][nj][1]);
                    const float e2 = __expf(sc[mi][nj][2]);
                    const float e3 = __expf(sc[mi][nj][3]);
                    rs0 += e0 + e1;
                    rs1 += e2 + e3;
                    pa[mi][nj][0] = pack_h2(e0, e1);
                    pa[mi][nj][1] = pack_h2(e2, e3);
                }
                rs0 += __shfl_xor_sync(0xffffffffu, rs0, 1);
                rs0 += __shfl_xor_sync(0xffffffffu, rs0, 2);
                rs1 += __shfl_xor_sync(0xffffffffu, rs1, 1);
                rs1 += __shfl_xor_sync(0xffffffffu, rs1, 2);
                l[2 * mi]     += rs0;
                l[2 * mi + 1] += rs1;
            }

#pragma unroll
            for (int sp = 0; sp < 2; sp++) {
                const int s = 2 * c2 + sp;
                uint32_t b0[8], b1[8];
#pragma unroll
                for (int nj = 0; nj < 8; nj++) {
                    b0[nj] = Vp[buf][8 * nj + g][8 * s + m];
                    b1[nj] = Vp[buf][8 * nj + g][8 * s + m + 4];
                }
#pragma unroll
                for (int mi = 0; mi < 2; mi++) {
                    const uint32_t a[4] = {pa[mi][2*sp][0],   pa[mi][2*sp][1],
                                           pa[mi][2*sp+1][0], pa[mi][2*sp+1][1]};
#pragma unroll
                    for (int nj = 0; nj < 8; nj++)
                        mma16(oc[mi][nj], a, b0[nj], b1[nj]);
                }
            }
        }

        __syncthreads();
        buf ^= 1;
    }

    // ---- epilogue: y = O / l, emit f16(4y) + residual ---------------------
    const int bb = bh >> 3;
    const int h  = bh & 7;
    float inv[4];
#pragma unroll
    for (int i = 0; i < 4; i++) inv[i] = ASCALE / l[i];   // fold x4

#pragma unroll
    for (int mi = 0; mi < 2; mi++) {
        const int r = 32 * w + 16 * mi + g;
        const size_t ro0 = ((size_t)(bb * NN + q0 + r    )) * DMODEL + h * DH;
        const size_t ro1 = ((size_t)(bb * NN + q0 + r + 8)) * DMODEL + h * DH;
#pragma unroll
        for (int nj = 0; nj < 8; nj++) {
            const int c = 8 * nj + 2 * m;
            const float t00 = oc[mi][nj][0] * inv[2 * mi];
            const float t01 = oc[mi][nj][1] * inv[2 * mi];
            const float t10 = oc[mi][nj][2] * inv[2 * mi + 1];
            const float t11 = oc[mi][nj][3] * inv[2 * mi + 1];
            const __half h00 = __float2half_rn(t00), h01 = __float2half_rn(t01);
            const __half h10 = __float2half_rn(t10), h11 = __float2half_rn(t11);
            *(__half2*)&Yh[ro0 + c] = __halves2half2(h00, h01);
            *(__half2*)&Yh[ro1 + c] = __halves2half2(h10, h11);
            *(__half2*)&Yl[ro0 + c] = __floats2half2_rn(t00 - __half2float(h00),
                                                        t01 - __half2float(h01));
            *(__half2*)&Yl[ro1 + c] = __floats2half2_rn(t10 - __half2float(h10),
                                                        t11 - __half2float(h11));
        }
    }
}

// ===========================================================================
extern "C" void kernel_launch(void* const* d_in, const int* in_sizes, int n_in,
                              void* d_out, int out_size)
{
    const float* x  = (const float*)d_in[0];
    const float* wq = (const float*)d_in[1];
    const float* bq = (const float*)d_in[2];
    const float* wk = (const float*)d_in[3];
    const float* bk = (const float*)d_in[4];
    const float* wv = (const float*)d_in[5];
    const float* bv = (const float*)d_in[6];
    const float* wo = (const float*)d_in[7];
    const float* bo = (const float*)d_in[8];
    float* out = (float*)d_out;

    __half *xh, *xl, *wh, *wl, *yh, *yl, *pq, *pk, *pvt;
    cudaGetSymbolAddress((void**)&xh,  s_xh);
    cudaGetSymbolAddress((void**)&xl,  s_xl);
    cudaGetSymbolAddress((void**)&wh,  s_wh);
    cudaGetSymbolAddress((void**)&wl,  s_wl);
    cudaGetSymbolAddress((void**)&yh,  s_yh);
    cudaGetSymbolAddress((void**)&yl,  s_yl);
    cudaGetSymbolAddress((void**)&pq,  h_q);
    cudaGetSymbolAddress((void**)&pk,  h_k);
    cudaGetSymbolAddress((void**)&pvt, h_vt);

    cudaFuncSetAttribute(proj_mma_kernel,
                         cudaFuncAttributeMaxDynamicSharedMemorySize,
                         PROJ_SMEM_BYTES);

    const int WN = DMODEL * DMODEL;            // 262144
    const int xn2 = MM * DMODEL / 2;           // 2097152
    const int wn2 = WN / 2;                    // 131072

    // one-time splits (x shared by Q/K/V; W reused by 64 CTAs each)
    conv_split_kernel<<<(xn2 + 255) / 256, 256>>>(x,  xh, xl, ASCALE, xn2);
    conv_split_kernel<<<(wn2 + 255) / 256, 256>>>(wq, wh + 0*WN, wl + 0*WN, WSCALE, wn2);
    conv_split_kernel<<<(wn2 + 255) / 256, 256>>>(wk, wh + 1*WN, wl + 1*WN, WSCALE, wn2);
    conv_split_kernel<<<(wn2 + 255) / 256, 256>>>(wv, wh + 2*WN, wl + 2*WN, WSCALE, wn2);
    conv_split_kernel<<<(wn2 + 255) / 256, 256>>>(wo, wh + 3*WN, wl + 3*WN, WSCALE, wn2);

    const dim3 pg(DMODEL / 128, MM / 128);     // (4, 64)

    proj_mma_kernel<<<pg, 256, PROJ_SMEM_BYTES>>>(xh, xl, wh + 0*WN, wl + 0*WN,
                                                  bq, nullptr, pq,  1);
    proj_mma_kernel<<<pg, 256, PROJ_SMEM_BYTES>>>(xh, xl, wh + 1*WN, wl + 1*WN,
                                                  bk, nullptr, pk,  2);
    proj_mma_kernel<<<pg, 256, PROJ_SMEM_BYTES>>>(xh, xl, wh + 2*WN, wl + 2*WN,
                                                  bv, nullptr, pvt, 3);

    attn_mma_kernel<<<dim3(NN / TQ, BB * HH), 128>>>(pq, pk, pvt, yh, yl);

    proj_mma_kernel<<<pg, 256, PROJ_SMEM_BYTES>>>(yh, yl, wh + 3*WN, wl + 3*WN,
                                                  bo, out, nullptr, 0);
}

// round 17
// speedup vs baseline: 1.9191x; 1.0765x over previous
#include <cuda_runtime.h>
#include <cuda_fp16.h>
#include <cstdint>
#include <math.h>

#define BB 2
#define NN 4096
#define DMODEL 512
#define HH 8
#define DH 64
#define MM (BB*NN)          // 8192 rows
#define TQ 128              // attention q tile
#define TK 64               // attention kv tile (2 chunks of 32)

// ---------------- scratch ----------------
__device__ __half s_xh[MM*DMODEL];     // f16(4*x)
__device__ __half s_xl[MM*DMODEL];     // residual
__device__ __half s_wh[4][DMODEL*DMODEL];   // f16(256*W), slots q,k,v,o
__device__ __half s_wl[4][DMODEL*DMODEL];
__device__ __half s_yh[MM*DMODEL];     // f16(4*y) attention output
__device__ __half s_yl[MM*DMODEL];
__device__ __half h_q [BB*HH*NN*DH];   // [bh][n][dh], pre-scaled by 0.125
__device__ __half h_k [BB*HH*NN*DH];   // [bh][n][dh]
__device__ __half h_vt[BB*HH*DH*NN];   // [bh][dh][n]  (V transposed)

// ===========================================================================
// Portable helpers (mma.sync f16 + cp.async, sm_80+ — valid at compute_103)
// ===========================================================================
__device__ __forceinline__ uint32_t pack_h2(float lo, float hi) {
    __half2 h = __floats2half2_rn(lo, hi);
    return *reinterpret_cast<uint32_t*>(&h);
}
// D(16x8,f32) += A(16x16,f16,row) * B(16x8,f16,col)   (layout per R14, proven)
__device__ __forceinline__ void mma16(float c[4], const uint32_t a[4],
                                      uint32_t b0, uint32_t b1)
{
    asm volatile(
        "mma.sync.aligned.m16n8k16.row.col.f32.f16.f16.f32 "
        "{%0,%1,%2,%3}, {%4,%5,%6,%7}, {%8,%9}, {%0,%1,%2,%3};"
        : "+f"(c[0]), "+f"(c[1]), "+f"(c[2]), "+f"(c[3])
        : "r"(a[0]), "r"(a[1]), "r"(a[2]), "r"(a[3]), "r"(b0), "r"(b1));
}
#define CP16(dst_u32, src_ptr) \
    asm volatile("cp.async.cg.shared.global [%0], [%1], 16;" \
                 :: "r"(dst_u32), "l"(src_ptr))
#define CP_COMMIT() asm volatile("cp.async.commit_group;" ::: "memory")
#define CP_WAIT1()  asm volatile("cp.async.wait_group 1;" ::: "memory")
#define CP_WAIT0()  asm volatile("cp.async.wait_group 0;" ::: "memory")

#define ASCALE 4.0f
#define WSCALE 256.0f
#define OSCALE (1.0f / (ASCALE * WSCALE))

// ===========================================================================
// One-time conversions: dst_hi = f16(scale*src), dst_lo = residual.
// conv_x: the activation tensor.  conv_w4: all four weight matrices in one
// launch (blockIdx.y selects the slot) — removes 3 launch/tail overheads.
// ===========================================================================
__global__ __launch_bounds__(256) void conv_x_kernel(
    const float* __restrict__ src, __half* __restrict__ hi,
    __half* __restrict__ lo, int n2)
{
    const int i = blockIdx.x * 256 + threadIdx.x;
    if (i >= n2) return;
    const float2 v = ((const float2*)src)[i];
    const float a = v.x * ASCALE, b = v.y * ASCALE;
    const __half ha = __float2half_rn(a), hb = __float2half_rn(b);
    ((__half2*)hi)[i] = __halves2half2(ha, hb);
    ((__half2*)lo)[i] = __floats2half2_rn(a - __half2float(ha),
                                          b - __half2float(hb));
}

__global__ __launch_bounds__(256) void conv_w4_kernel(
    const float* __restrict__ w0, const float* __restrict__ w1,
    const float* __restrict__ w2, const float* __restrict__ w3,
    __half* __restrict__ hi, __half* __restrict__ lo, int n2)
{
    const int i = blockIdx.x * 256 + threadIdx.x;
    if (i >= n2) return;
    const int slot = blockIdx.y;
    const float* src = (slot == 0) ? w0 : (slot == 1) ? w1
                     : (slot == 2) ? w2 : w3;
    const float2 v = ((const float2*)src)[i];
    const float a = v.x * WSCALE, b = v.y * WSCALE;
    const __half ha = __float2half_rn(a), hb = __float2half_rn(b);
    ((__half2*)(hi + (size_t)slot * DMODEL * DMODEL))[i] =
        __halves2half2(ha, hb);
    ((__half2*)(lo + (size_t)slot * DMODEL * DMODEL))[i] =
        __floats2half2_rn(a - __half2float(ha), b - __half2float(hb));
}

// ===========================================================================
// Projection GEMM, 3xFP16-split, pre-converted inputs + cp.async pipeline.
// NOW 2 CTAs/SM (launch_bounds(256,2); 2x80KB smem = 160KB <= 228KB):
// grid 256 fits in one wave (296 slots) -> no idle tail, cross-CTA overlap.
// Loop per chunk: cp.async(c+1, buf^1) -> wait(1) -> bar -> 48 mma16 -> bar.
// Epilogue modes: 0 = f32 (+bias) [O]; 1 = Q f16*0.125; 2 = K f16; 3 = Vt f16.
// ===========================================================================
#define PKC 16
#define PROJ_SMEM_BYTES (2 * 2 * 128 * 20 * 4)   // 81920

__global__ __launch_bounds__(256, 2) void proj_mma_kernel(
    const __half* __restrict__ Ah, const __half* __restrict__ Al,
    const __half* __restrict__ Wh, const __half* __restrict__ Wl,
    const float* __restrict__ bias, float* __restrict__ dstf,
    __half* __restrict__ dsth, int mode)
{
    extern __shared__ uint32_t psm[];
    uint32_t (*As)[128][20] = (uint32_t(*)[128][20])psm;
    uint32_t (*Ws)[128][20] = (uint32_t(*)[128][20])(psm + 2 * 128 * 20);

    const int tid  = threadIdx.x;
    const int lane = tid & 31;
    const int w    = tid >> 5;
    const int g    = lane >> 2;
    const int m    = lane & 3;
    const int wm   = w & 1;
    const int wn   = w >> 1;
    const int m0   = blockIdx.y * 128;
    const int e0   = blockIdx.x * 128;

    const uint32_t as_base = (uint32_t)__cvta_generic_to_shared(&As[0][0][0]);
    const uint32_t ws_base = (uint32_t)__cvta_generic_to_shared(&Ws[0][0][0]);

    float acc[4][4][4];
#pragma unroll
    for (int mi = 0; mi < 4; mi++)
#pragma unroll
        for (int nj = 0; nj < 4; nj++)
#pragma unroll
            for (int j = 0; j < 4; j++) acc[mi][nj][j] = 0.f;

    // chunk map: 1024 16B-chunks per k-chunk (A:512 + W:512), 4 per thread.
#define PROJ_ISSUE(cc, bi) do {                                              \
        _Pragma("unroll")                                                    \
        for (int j = 0; j < 4; j++) {                                        \
            const int ci  = 4 * tid + j;                                     \
            const int op  = ci >> 9;                                         \
            const int ci9 = ci & 511;                                        \
            const int row = ci9 >> 2;                                        \
            const int sub = ci9 & 3;                                         \
            const int woff = (sub < 2) ? sub * 4 : 8 + (sub - 2) * 4;        \
            const uint32_t dw = (uint32_t)(((((bi) * 128 + row) * 20) + woff) * 4); \
            const int ko = (cc) * PKC + (sub & 1) * 8;                       \
            if (op == 0) {                                                   \
                const __half* src = ((sub < 2) ? Ah : Al)                    \
                    + (size_t)(m0 + row) * DMODEL + ko;                      \
                CP16(as_base + dw, src);                                     \
            } else {                                                         \
                const __half* src = ((sub < 2) ? Wh : Wl)                    \
                    + (size_t)(e0 + row) * DMODEL + ko;                      \
                CP16(ws_base + dw, src);                                     \
            }                                                                \
        }                                                                    \
        CP_COMMIT();                                                         \
    } while (0)

    PROJ_ISSUE(0, 0);

    const int NC = DMODEL / PKC;     // 32
    int buf = 0;
    for (int c = 0; c < NC; c++) {
        if (c + 1 < NC) { PROJ_ISSUE(c + 1, buf ^ 1); CP_WAIT1(); }
        else            { CP_WAIT0(); }
        __syncthreads();                    // chunk c visible CTA-wide

        uint32_t ah[4][4], al[4][4];
#pragma unroll
        for (int mi = 0; mi < 4; mi++) {
            const int r = 64 * wm + 16 * mi + g;
            ah[mi][0] = As[buf][r    ][m];     ah[mi][1] = As[buf][r + 8][m];
            ah[mi][2] = As[buf][r    ][m + 4]; ah[mi][3] = As[buf][r + 8][m + 4];
            al[mi][0] = As[buf][r    ][8 + m];     al[mi][1] = As[buf][r + 8][8 + m];
            al[mi][2] = As[buf][r    ][8 + m + 4]; al[mi][3] = As[buf][r + 8][8 + m + 4];
        }
        uint32_t bh[4][2], bl[4][2];
#pragma unroll
        for (int nj = 0; nj < 4; nj++) {
            const int n = 32 * wn + 8 * nj + g;
            bh[nj][0] = Ws[buf][n][m];     bh[nj][1] = Ws[buf][n][m + 4];
            bl[nj][0] = Ws[buf][n][8 + m]; bl[nj][1] = Ws[buf][n][8 + m + 4];
        }
#pragma unroll
        for (int mi = 0; mi < 4; mi++)
#pragma unroll
            for (int nj = 0; nj < 4; nj++) {
                mma16(acc[mi][nj], ah[mi], bh[nj][0], bh[nj][1]);
                mma16(acc[mi][nj], ah[mi], bl[nj][0], bl[nj][1]);
                mma16(acc[mi][nj], al[mi], bh[nj][0], bh[nj][1]);
            }

        __syncthreads();                    // buf consumed before next issue
        buf ^= 1;
    }

    // ---- epilogue ---------------------------------------------------------
#pragma unroll
    for (int mi = 0; mi < 4; mi++) {
        const int r0 = m0 + 64 * wm + 16 * mi + g;
#pragma unroll
        for (int nj = 0; nj < 4; nj++) {
            const int e = e0 + 32 * wn + 8 * nj + 2 * m;
            const float b0 = bias[e], b1 = bias[e + 1];
#pragma unroll
            for (int half = 0; half < 2; half++) {
                const int mr = r0 + 8 * half;
                float v0 = acc[mi][nj][2*half]   * OSCALE + b0;
                float v1 = acc[mi][nj][2*half+1] * OSCALE + b1;
                if (mode == 0) {
                    *(float2*)&dstf[(size_t)mr * DMODEL + e] =
                        make_float2(v0, v1);
                } else {
                    const int bb = mr >> 12;
                    const int n  = mr & (NN - 1);
                    const int h  = e >> 6;
                    const int d  = e & 63;
                    if (mode == 3) {           // V transposed [bh][dh][n]
                        __half* base = dsth + ((size_t)(bb*HH + h) * DH) * NN + n;
                        base[(size_t)d       * NN] = __float2half_rn(v0);
                        base[(size_t)(d + 1) * NN] = __float2half_rn(v1);
                    } else {                   // Q/K [bh][n][dh]
                        if (mode == 1) { v0 *= 0.125f; v1 *= 0.125f; }
                        __half2 hv = __floats2half2_rn(v0, v1);
                        *(__half2*)&dsth[((size_t)((bb*HH + h) * NN + n)) * DH + d] = hv;
                    }
                }
            }
        }
    }
}

// ===========================================================================
// Attention (EXACT R15/R16 structure, proven 269us).
// ===========================================================================
__global__ __launch_bounds__(128, 2)
void attn_mma_kernel(const __half* __restrict__ Qh,
                     const __half* __restrict__ Kh,
                     const __half* __restrict__ Vth,
                     __half* __restrict__ Yh, __half* __restrict__ Yl)
{
    __shared__ uint32_t Ks[2][64][36];
    __shared__ uint32_t Vp[2][64][36];

    const int tid  = threadIdx.x;
    const int lane = tid & 31;
    const int w    = tid >> 5;
    const int g    = lane >> 2;
    const int m    = lane & 3;
    const int q0   = blockIdx.x * TQ;
    const int bh   = blockIdx.y;

    const __half* Kb  = Kh  + (size_t)bh * NN * DH;
    const __half* Vtb = Vth + (size_t)bh * DH * NN;

    uint32_t qa[2][4][4];
    {
        const __half* Qw = Qh + (size_t)bh * NN * DH
                              + (size_t)(q0 + 32 * w) * DH;
#pragma unroll
        for (int mi = 0; mi < 2; mi++)
#pragma unroll
            for (int s = 0; s < 4; s++) {
                const int r = 16 * mi + g;
                const int c = 16 * s + 2 * m;
                qa[mi][s][0] = *(const uint32_t*)(Qw + (r    ) * DH + c);
                qa[mi][s][1] = *(const uint32_t*)(Qw + (r + 8) * DH + c);
                qa[mi][s][2] = *(const uint32_t*)(Qw + (r    ) * DH + c + 8);
                qa[mi][s][3] = *(const uint32_t*)(Qw + (r + 8) * DH + c + 8);
            }
    }

    float oc[2][8][4];
    float l[4];
#pragma unroll
    for (int mi = 0; mi < 2; mi++)
#pragma unroll
        for (int nj = 0; nj < 8; nj++)
#pragma unroll
            for (int j = 0; j < 4; j++) oc[mi][nj][j] = 0.f;
#pragma unroll
    for (int i = 0; i < 4; i++) l[i] = 0.f;

    const uint32_t ks_base = (uint32_t)__cvta_generic_to_shared(&Ks[0][0][0]);
    const uint32_t vp_base = (uint32_t)__cvta_generic_to_shared(&Vp[0][0][0]);

#define ATTN_ISSUE(tt, bi) do {                                             \
        _Pragma("unroll")                                                   \
        for (int j = 0; j < 4; j++) {                                       \
            const int ci  = 4 * tid + j;                                    \
            const int row = ci >> 3;                                        \
            const int off = ci & 7;                                         \
            const uint32_t dw = (uint32_t)((((bi) * 64 + row) * 36 + off * 4) * 4); \
            CP16(ks_base + dw, Kb  + ((size_t)((tt) * 64 + row)) * DH + off * 8);   \
            CP16(vp_base + dw, Vtb + (size_t)row * NN + (tt) * 64 + off * 8);       \
        }                                                                   \
        CP_COMMIT();                                                        \
    } while (0)

    ATTN_ISSUE(0, 0);

    const int T = NN / TK;      // 32
    int buf = 0;
    for (int t = 0; t < T; t++) {
        if (t + 1 < T) { ATTN_ISSUE(t + 1, buf ^ 1); CP_WAIT1(); }
        else           { CP_WAIT0(); }
        __syncthreads();

#pragma unroll
        for (int c2 = 0; c2 < 2; c2++) {
            float sc[2][4][4];
#pragma unroll
            for (int mi = 0; mi < 2; mi++)
#pragma unroll
                for (int nj = 0; nj < 4; nj++)
#pragma unroll
                    for (int j = 0; j < 4; j++) sc[mi][nj][j] = 0.f;

#pragma unroll
            for (int s = 0; s < 4; s++) {
                uint32_t b0[4], b1[4];
#pragma unroll
                for (int nj = 0; nj < 4; nj++) {
                    const int row = 32 * c2 + 8 * nj + g;
                    b0[nj] = Ks[buf][row][8 * s + m];
                    b1[nj] = Ks[buf][row][8 * s + m + 4];
                }
#pragma unroll
                for (int mi = 0; mi < 2; mi++)
#pragma unroll
                    for (int nj = 0; nj < 4; nj++)
                        mma16(sc[mi][nj], qa[mi][s], b0[nj], b1[nj]);
            }

            uint32_t pa[2][4][2];
#pragma unroll
            for (int mi = 0; mi < 2; mi++) {
                float rs0 = 0.f, rs1 = 0.f;
#pragma unroll
                for (int nj = 0; nj < 4; nj++) {
                    const float e0 = __expf(sc[mi][nj][0]);
                    const float e1 = __expf(sc[mi][nj][1]);
                    const float e2 = __expf(sc[mi][nj][2]);
                    const float e3 = __expf(sc[mi][nj][3]);
                    rs0 += e0 + e1;
                    rs1 += e2 + e3;
                    pa[mi][nj][0] = pack_h2(e0, e1);
                    pa[mi][nj][1] = pack_h2(e2, e3);
                }
                rs0 += __shfl_xor_sync(0xffffffffu, rs0, 1);
                rs0 += __shfl_xor_sync(0xffffffffu, rs0, 2);
                rs1 += __shfl_xor_sync(0xffffffffu, rs1, 1);
                rs1 += __shfl_xor_sync(0xffffffffu, rs1, 2);
                l[2 * mi]     += rs0;
                l[2 * mi + 1] += rs1;
            }

#pragma unroll
            for (int sp = 0; sp < 2; sp++) {
                const int s = 2 * c2 + sp;
                uint32_t b0[8], b1[8];
#pragma unroll
                for (int nj = 0; nj < 8; nj++) {
                    b0[nj] = Vp[buf][8 * nj + g][8 * s + m];
                    b1[nj] = Vp[buf][8 * nj + g][8 * s + m + 4];
                }
#pragma unroll
                for (int mi = 0; mi < 2; mi++) {
                    const uint32_t a[4] = {pa[mi][2*sp][0],   pa[mi][2*sp][1],
                                           pa[mi][2*sp+1][0], pa[mi][2*sp+1][1]};
#pragma unroll
                    for (int nj = 0; nj < 8; nj++)
                        mma16(oc[mi][nj], a, b0[nj], b1[nj]);
                }
            }
        }

        __syncthreads();
        buf ^= 1;
    }

    // ---- epilogue: y = O / l, emit f16(4y) + residual ---------------------
    const int bb = bh >> 3;
    const int h  = bh & 7;
    float inv[4];
#pragma unroll
    for (int i = 0; i < 4; i++) inv[i] = ASCALE / l[i];   // fold x4

#pragma unroll
    for (int mi = 0; mi < 2; mi++) {
        const int r = 32 * w + 16 * mi + g;
        const size_t ro0 = ((size_t)(bb * NN + q0 + r    )) * DMODEL + h * DH;
        const size_t ro1 = ((size_t)(bb * NN + q0 + r + 8)) * DMODEL + h * DH;
#pragma unroll
        for (int nj = 0; nj < 8; nj++) {
            const int c = 8 * nj + 2 * m;
            const float t00 = oc[mi][nj][0] * inv[2 * mi];
            const float t01 = oc[mi][nj][1] * inv[2 * mi];
            const float t10 = oc[mi][nj][2] * inv[2 * mi + 1];
            const float t11 = oc[mi][nj][3] * inv[2 * mi + 1];
            const __half h00 = __float2half_rn(t00), h01 = __float2half_rn(t01);
            const __half h10 = __float2half_rn(t10), h11 = __float2half_rn(t11);
            *(__half2*)&Yh[ro0 + c] = __halves2half2(h00, h01);
            *(__half2*)&Yh[ro1 + c] = __halves2half2(h10, h11);
            *(__half2*)&Yl[ro0 + c] = __floats2half2_rn(t00 - __half2float(h00),
                                                        t01 - __half2float(h01));
            *(__half2*)&Yl[ro1 + c] = __floats2half2_rn(t10 - __half2float(h10),
                                                        t11 - __half2float(h11));
        }
    }
}

// ===========================================================================
extern "C" void kernel_launch(void* const* d_in, const int* in_sizes, int n_in,
                              void* d_out, int out_size)
{
    const float* x  = (const float*)d_in[0];
    const float* wq = (const float*)d_in[1];
    const float* bq = (const float*)d_in[2];
    const float* wk = (const float*)d_in[3];
    const float* bk = (const float*)d_in[4];
    const float* wv = (const float*)d_in[5];
    const float* bv = (const float*)d_in[6];
    const float* wo = (const float*)d_in[7];
    const float* bo = (const float*)d_in[8];
    float* out = (float*)d_out;

    __half *xh, *xl, *wh, *wl, *yh, *yl, *pq, *pk, *pvt;
    cudaGetSymbolAddress((void**)&xh,  s_xh);
    cudaGetSymbolAddress((void**)&xl,  s_xl);
    cudaGetSymbolAddress((void**)&wh,  s_wh);
    cudaGetSymbolAddress((void**)&wl,  s_wl);
    cudaGetSymbolAddress((void**)&yh,  s_yh);
    cudaGetSymbolAddress((void**)&yl,  s_yl);
    cudaGetSymbolAddress((void**)&pq,  h_q);
    cudaGetSymbolAddress((void**)&pk,  h_k);
    cudaGetSymbolAddress((void**)&pvt, h_vt);

    cudaFuncSetAttribute(proj_mma_kernel,
                         cudaFuncAttributeMaxDynamicSharedMemorySize,
                         PROJ_SMEM_BYTES);

    const int WN = DMODEL * DMODEL;            // 262144
    const int xn2 = MM * DMODEL / 2;           // 2097152
    const int wn2 = WN / 2;                    // 131072

    conv_x_kernel<<<(xn2 + 255) / 256, 256>>>(x, xh, xl, xn2);
    conv_w4_kernel<<<dim3((wn2 + 255) / 256, 4), 256>>>(wq, wk, wv, wo,
                                                        wh, wl, wn2);

    const dim3 pg(DMODEL / 128, MM / 128);     // (4, 64)

    proj_mma_kernel<<<pg, 256, PROJ_SMEM_BYTES>>>(xh, xl, wh + 0*WN, wl + 0*WN,
                                                  bq, nullptr, pq,  1);
    proj_mma_kernel<<<pg, 256, PROJ_SMEM_BYTES>>>(xh, xl, wh + 1*WN, wl + 1*WN,
                                                  bk, nullptr, pk,  2);
    proj_mma_kernel<<<pg, 256, PROJ_SMEM_BYTES>>>(xh, xl, wh + 2*WN, wl + 2*WN,
                                                  bv, nullptr, pvt, 3);

    attn_mma_kernel<<<dim3(NN / TQ, BB * HH), 128>>>(pq, pk, pvt, yh, yl);

    proj_mma_kernel<<<pg, 256, PROJ_SMEM_BYTES>>>(yh, yl, wh + 3*WN, wl + 3*WN,
                                                  bo, out, nullptr, 0);
}